// round 17
// baseline (speedup 1.0000x reference)
#include <cuda_runtime.h>
#include <cuda_bf16.h>

// Problem constants (fixed by the dataset): B=32, L=256, V=50000, C=128
#define CC   128
#define LL   256
#define BDIM 128

typedef unsigned int u32;
typedef unsigned short u16;

__device__ __forceinline__ u32 bf2_fma(u32 a, u32 b, u32 c) {
    u32 d; asm("fma.rn.bf16x2 %0, %1, %2, %3;" : "=r"(d) : "r"(a), "r"(b), "r"(c)); return d;
}
__device__ __forceinline__ u32 bf2_add(u32 a, u32 b) {
    u32 d; asm("add.rn.bf16x2 %0, %1, %2;" : "=r"(d) : "r"(a), "r"(b)); return d;
}
__device__ __forceinline__ u32 bf2_pack(float lo, float hi) {
    u32 d; asm("cvt.rn.bf16x2.f32 %0, %1, %2;" : "=r"(d) : "f"(hi), "f"(lo)); return d;
}
__device__ __forceinline__ float bf2_lo(u32 v) { return __uint_as_float(v << 16); }
__device__ __forceinline__ float bf2_hi(u32 v) { return __uint_as_float(v & 0xFFFF0000u); }
__device__ __forceinline__ float frcp_ap(float x) {
    float r; asm("rcp.approx.f32 %0, %1;" : "=f"(r) : "f"(x)); return r;
}
// fast fp32 -> bf16 bits (round-to-nearest): IADD+SHF, not F2FP
__device__ __forceinline__ u16 f2bf_bits(float x) {
    return (u16)((__float_as_uint(x) + 0x8000u) >> 16);
}
// 4-byte cp.async global->shared (LDGSTS): no destination register, so no
// per-iteration register rotation waiting on the load.
__device__ __forceinline__ void cp_async4(u32 smem_addr, const void* gptr) {
    asm volatile("cp.async.ca.shared.global [%0], [%1], 4;"
                 :: "r"(smem_addr), "l"(gptr));
}
__device__ __forceinline__ void cp_commit() {
    asm volatile("cp.async.commit_group;");
}
__device__ __forceinline__ void cp_wait4() {
    asm volatile("cp.async.wait_group 4;");
}

__global__ __launch_bounds__(BDIM, 1)
void crf_fwd_kernel(const int*   __restrict__ tokens,
                    const int*   __restrict__ target,
                    const float* __restrict__ mask,
                    const float* __restrict__ st,      // state_table [V, C]
                    const float* __restrict__ trans,   // trans_matrix [C, C]
                    float*       __restrict__ out)     // [B]
{
    // p stored ONCE as bf16 pairs: word k = {p[2k](lo), p[2k+1](hi)}, 64 words,
    // double buffered. All threads read the same addresses (pure broadcast).
    __shared__ __align__(16) u32 p2_s[2][64];
    __shared__ int   tok_s[LL + 8];   // padded: tok_s[t>=LL] = tok_s[LL-1]
    __shared__ float m_s[LL + 8];     // padded with last mask (value unused)
    __shared__ float ring_s[8][CC];   // emission prefetch ring (cp.async)
    __shared__ float red_s[4], red2_s[4];

    const int b   = blockIdx.x;
    const int tid = threadIdx.x;
    const int w   = tid >> 5;
    const int l   = tid & 31;
    const int j   = tid;              // this thread owns state j (0..127)

    const u32 ring_base = (u32)__cvta_generic_to_shared(&ring_s[0][j]);

    // ---- stage tokens/mask (LL = 2*BDIM) + target-energy partial ----
    float tgt_part = 0.0f;
#pragma unroll
    for (int t = tid; t < LL; t += BDIM) {
        tok_s[t] = tokens[b * LL + t];
        m_s[t]   = mask[b * LL + t];
        const int tg   = target[b * LL + t];
        const int prev = (t == 0) ? (CC - 1) : target[b * LL + t - 1];
        tgt_part += (trans[prev * CC + tg] + st[tok_s[t] * CC + tg]) * m_s[t];
    }

    // ---- E2[k] = bf16x2{ exp(trans[2k][j]), exp(trans[2k+1][j]) }, k = 0..63 ----
    u32 E2[64];
#pragma unroll
    for (int k = 0; k < 64; ++k)
        E2[k] = bf2_pack(__expf(trans[(2 * k) * CC + j]),
                         __expf(trans[(2 * k + 1) * CC + j]));
    __syncthreads();   // tok_s/m_s visible

    // pad token/mask tails (clamped) so the loop needs no min()
    if (tid < 8) {
        tok_s[LL + tid] = tok_s[LL - 1];
        m_s[LL + tid]   = m_s[LL - 1];
    }

    // ---- init: p_1[j] = exp((trans[C-1][j] + em_0[j]) * m0) ----
    u16* pb0 = reinterpret_cast<u16*>(&p2_s[0][0]);
    u16* pb1 = reinterpret_cast<u16*>(&p2_s[1][0]);
    const float m0 = m_s[0];
    float p = __expf((trans[(CC - 1) * CC + j] + st[tok_s[0] * CC + j]) * m0);
    pb0[j] = f2bf_bits(p);

    // emission exp pipeline: ec = exp(em[t]), en = exp(em[t+1])
    float ec = __expf(st[tok_s[1] * CC + j]);
    float en = __expf(st[tok_s[2] * CC + j]);

    // prologue: prefetch emission rows 3..6 into ring slots 3..6 (4 groups)
#pragma unroll
    for (int r = 3; r <= 6; ++r) {
        cp_async4(ring_base + (u32)((r & 7) * CC * 4), st + tok_s[r] * CC + j);
        cp_commit();
    }

    float S  = 0.0f;   // accumulated shift; true part[j] = log p[j] + S
    float mt = m_s[1];
    float mn = m_s[2];
    __syncthreads();

    // lagged normalizer: divide step t by the p[0] captured from the PREVIOUS
    // matvec's first LDS word (any positive scalar is exact here).
    float p0c  = bf2_lo(p2_s[0][0]);
    float invc = frcp_ap(p0c);

    // ---- sequential scan: in-thread full matvec; head is pure registers ----
    for (int t = 1; t < LL; ++t) {
        const int rb = (t - 1) & 1, wb = t & 1;

        // head: all-register precompute
        //   p_new = s*A + Cc  ==  (1-mt)*p + mt*(s*ec*invc)
        const float A  = ec * invc * mt;
        const float Cc = p * (1.0f - mt);

        // fire-and-forget prefetch of emission row t+6 into the ring
        cp_async4(ring_base + (u32)(((t + 6) & 7) * CC * 4),
                  st + tok_s[t + 6] * CC + j);
        cp_commit();

        // s_j = sum_i p[i] * E[i][j]: 64 HFMA2 over i-pairs, 8 indep chains
        const uint4* ap = reinterpret_cast<const uint4*>(&p2_s[rb][0]);
        u32 nrm = 0;                                 // captures {p[0],p[1]} word
        u32 a0 = 0, a1 = 0, a2 = 0, a3 = 0, a4 = 0, a5 = 0, a6 = 0, a7 = 0;
#pragma unroll
        for (int k = 0; k < 8; ++k) {
            const uint4 v0 = ap[2 * k];
            const uint4 v1 = ap[2 * k + 1];
            if (k == 0) nrm = v0.x;                  // free capture of p[0]
            a0 = bf2_fma(v0.x, E2[8 * k + 0], a0);
            a1 = bf2_fma(v0.y, E2[8 * k + 1], a1);
            a2 = bf2_fma(v0.z, E2[8 * k + 2], a2);
            a3 = bf2_fma(v0.w, E2[8 * k + 3], a3);
            a4 = bf2_fma(v1.x, E2[8 * k + 4], a4);
            a5 = bf2_fma(v1.y, E2[8 * k + 5], a5);
            a6 = bf2_fma(v1.z, E2[8 * k + 6], a6);
            a7 = bf2_fma(v1.w, E2[8 * k + 7], a7);
        }
        // combine: three bf16x2 levels (7 instrs), then 1 unpack-add
        const u32 c0 = bf2_add(a0, a1), c1 = bf2_add(a2, a3);
        const u32 c2 = bf2_add(a4, a5), c3 = bf2_add(a6, a7);
        const u32 d0 = bf2_add(c0, c1), d1 = bf2_add(c2, c3);
        const u32 e  = bf2_add(d0, d1);
        const float s = bf2_lo(e) + bf2_hi(e);

        // one-FMA tail, fast bf16 store
        p = fmaf(s, A, Cc);
        ((wb) ? pb1 : pb0)[j] = f2bf_bits(p);

        // ---- pre-barrier shadow work (absorbed by DEFER_BLOCKING bar) ----
        if (j == 0) S += mt * __logf(p0c);           // log of the divisor we used
        p0c  = bf2_lo(nrm);                          // next step's normalizer
        invc = frcp_ap(p0c);
        mt   = mn;
        mn   = m_s[t + 2];
        // emission rotate: wait only for the copy issued 4 steps ago, then LDS
        cp_wait4();
        const float raw = ring_s[(t + 2) & 7][j];    // row t+2 (guaranteed done)
        ec = en;
        en = __expf(raw);
        __syncthreads();
    }

    // ---- epilogue: loss = S + log(sum_j p[j]) - tgt_energy ----
    float c = p;                                     // each state counted once
#pragma unroll
    for (int o = 16; o; o >>= 1) c += __shfl_xor_sync(0xffffffffu, c, o);
    float tp = tgt_part;
#pragma unroll
    for (int o = 16; o; o >>= 1) tp += __shfl_xor_sync(0xffffffffu, tp, o);
    if (l == 0) { red_s[w] = c; red2_s[w] = tp; }
    __syncthreads();

    if (tid == 0) {
        const float ss = (red_s[0] + red_s[1]) + (red_s[2] + red_s[3]);
        const float ts = (red2_s[0] + red2_s[1]) + (red2_s[2] + red2_s[3]);
        out[b] = S + logf(ss) - ts;
    }
}

extern "C" void kernel_launch(void* const* d_in, const int* in_sizes, int n_in,
                              void* d_out, int out_size)
{
    const int*   tokens = (const int*)  d_in[0];
    const int*   target = (const int*)  d_in[1];
    const float* mask   = (const float*)d_in[2];
    const float* st     = (const float*)d_in[3];
    const float* trans  = (const float*)d_in[4];
    float*       out    = (float*)d_out;

    const int B = in_sizes[0] / LL;   // 32
    crf_fwd_kernel<<<B, BDIM>>>(tokens, target, mask, st, trans, out);
}